// round 15
// baseline (speedup 1.0000x reference)
#include <cuda_runtime.h>
#include <cuda_bf16.h>
#include <cstdint>

#define HWPIX 3136
#define NELEM 51380224
#define TFAC 0.05f

__device__ __nv_bfloat16 g_xhi[NELEM], g_xlo[NELEM];
__device__ __nv_bfloat16 g_ahi[NELEM], g_alo[NELEM];
__device__ float g_buf1[NELEM], g_buf2[NELEM];
__device__ __nv_bfloat16 g_ws[2][9][65536];   // sign weights [sel][pos][co*256+ci]
__device__ unsigned g_absw[2], g_absx;
__device__ double g_wsum[2];
__device__ unsigned long long g_wcnt[2];
__device__ double g_bnsum[2][256], g_bnsq[2][256];
__device__ float g_bnscale[2][256], g_bnshift[2][256];

__device__ __forceinline__ void mma16816(float* d, const uint32_t* a,
                                         const uint32_t* b) {
    asm volatile(
        "mma.sync.aligned.m16n8k16.row.col.f32.bf16.bf16.f32 "
        "{%0,%1,%2,%3}, {%4,%5,%6,%7}, {%8,%9}, {%0,%1,%2,%3};"
        : "+f"(d[0]), "+f"(d[1]), "+f"(d[2]), "+f"(d[3])
        : "r"(a[0]), "r"(a[1]), "r"(a[2]), "r"(a[3]), "r"(b[0]), "r"(b[1]));
}
__device__ __forceinline__ void ldsm4(uint32_t* r, uint32_t addr) {
    asm volatile("ldmatrix.sync.aligned.m8n8.x4.shared.b16 {%0,%1,%2,%3}, [%4];"
                 : "=r"(r[0]), "=r"(r[1]), "=r"(r[2]), "=r"(r[3]) : "r"(addr));
}

// ---- launch 1 ----
__global__ void init_k() {
    int t = threadIdx.x;
    if (t < 2) { g_absw[t] = 0u; g_wsum[t] = 0.0; g_wcnt[t] = 0ull; }
    if (t == 2) g_absx = 0u;
    g_bnsum[0][t] = 0.0; g_bnsum[1][t] = 0.0;
    g_bnsq[0][t] = 0.0;  g_bnsq[1][t] = 0.0;
}

// ---- launch 2: absmax of w1 / w2 / x ----
__global__ void absmax3_k(const float* __restrict__ w1,
                          const float* __restrict__ w2,
                          const float* __restrict__ x) {
    int sel = blockIdx.y;
    float m = 0.f;
    if (sel < 2) {
        const float* w = sel ? w2 : w1;
        for (int i = blockIdx.x * blockDim.x + threadIdx.x; i < 589824;
             i += gridDim.x * blockDim.x)
            m = fmaxf(m, fabsf(w[i]));
    } else {
        const float4* p = (const float4*)x;
        for (size_t i = (size_t)blockIdx.x * blockDim.x + threadIdx.x;
             i < NELEM / 4; i += (size_t)gridDim.x * blockDim.x) {
            float4 v = p[i];
            m = fmaxf(m, fmaxf(fmaxf(fabsf(v.x), fabsf(v.y)),
                               fmaxf(fabsf(v.z), fabsf(v.w))));
        }
    }
#pragma unroll
    for (int o = 16; o; o >>= 1) m = fmaxf(m, __shfl_xor_sync(~0u, m, o));
    __shared__ float sm[8];
    if ((threadIdx.x & 31) == 0) sm[threadIdx.x >> 5] = m;
    __syncthreads();
    if (threadIdx.x == 0) {
        float mm = sm[0];
#pragma unroll
        for (int i = 1; i < 8; i++) mm = fmaxf(mm, sm[i]);
        atomicMax(sel < 2 ? &g_absw[sel] : &g_absx, __float_as_uint(mm));
    }
}

// ---- launch 3: wsum + wsign + xprep fused ----
__global__ void prep_k(const float* __restrict__ w1, const float* __restrict__ w2,
                       const float* __restrict__ x) {
    int b = blockIdx.x, tid = threadIdx.x;
    if (b < 512) {
        int sel = b >> 8;
        const float* w = sel ? w2 : w1;
        float th = TFAC * __uint_as_float(g_absw[sel]);
        double s = 0.0;
        unsigned c = 0;
        for (int i = (b & 255) * 256 + tid; i < 589824; i += 65536) {
            float v = w[i];
            if (v >= th || v <= -th) { s += (double)fabsf(v); c++; }
        }
#pragma unroll
        for (int o = 16; o; o >>= 1) {
            s += __shfl_xor_sync(~0u, s, o);
            c += __shfl_xor_sync(~0u, c, o);
        }
        __shared__ double ss[8];
        __shared__ unsigned sc_[8];
        if ((tid & 31) == 0) { ss[tid >> 5] = s; sc_[tid >> 5] = c; }
        __syncthreads();
        if (tid == 0) {
            double S = 0.0; unsigned long long C = 0ull;
#pragma unroll
            for (int i = 0; i < 8; i++) { S += ss[i]; C += sc_[i]; }
            atomicAdd(&g_wsum[sel], S);
            atomicAdd(&g_wcnt[sel], C);
        }
    } else if (b < 1024) {
        int sel = (b - 512) >> 8;
        const float* w = sel ? w2 : w1;
        float th = TFAC * __uint_as_float(g_absw[sel]);
        int i = ((b - 512) & 255) * 256 + tid;
#pragma unroll
        for (int k = 0; k < 9; k++) {
            float v = w[(size_t)i * 9 + k];
            float s = (v >= th) ? 1.f : ((v < -th) ? -1.f : 0.f);
            g_ws[sel][k][i] = __float2bfloat16(s);
        }
    } else {
        __shared__ float s[32][33];
        int idx = b - 1024;
        int img = idx / 784, rem = idx % 784;
        int c0 = (rem / 98) * 32, p0 = (rem % 98) * 32;
        int tx = tid & 31, ty = tid >> 5;
#pragma unroll
        for (int r = 0; r < 4; r++)
            s[ty + r * 8][tx] =
                x[((size_t)img * 256 + c0 + ty + r * 8) * HWPIX + p0 + tx];
        __syncthreads();
#pragma unroll
        for (int r = 0; r < 4; r++) {
            float v = s[tx][ty + r * 8];
            __nv_bfloat16 h = __float2bfloat16(v);
            __nv_bfloat16 l = __float2bfloat16(v - __bfloat162float(h));
            size_t d = ((size_t)img * HWPIX + p0 + ty + r * 8) * 256 + c0 + tx;
            g_xhi[d] = h; g_xlo[d] = l;
        }
    }
}

// ---- conv: CTA 128co x 128pix, bf16 HMMA, ldmatrix fragment loads ----
#define SB_LO 20800
#define SA    41600
#define SMSZ  62080

__device__ __forceinline__ void ldgA(uint4* v, int which, int pos, int co0,
                                     int ci0, int tid) {
    const uint4* p = (const uint4*)(g_ws[which][pos] +
                                    (size_t)(co0 + (tid >> 1)) * 256 + ci0 +
                                    (tid & 1) * 16);
    v[0] = p[0]; v[1] = p[1];
}
__device__ __forceinline__ void stsA(char* base, const uint4* v, int tid) {
    char* d = base + (tid >> 1) * 80 + (tid & 1) * 32;
    *(uint4*)d = v[0];
    *(uint4*)(d + 16) = v[1];
}

__global__ void __launch_bounds__(256, 2) conv_k(int which) {
    extern __shared__ char smc[];
    const int tid = threadIdx.x, lane = tid & 31, warp = tid >> 5;
    const int g = lane >> 2, tg = lane & 3;
    const int sub = lane >> 3, rr = lane & 7;
    const int wco = (warp >> 2) * 64, wpix = (warp & 3) * 32;
    const int h0 = blockIdx.x * 2, co0 = blockIdx.y * 128, img = blockIdx.z;
    const __nv_bfloat16* __restrict__ xhi = which ? g_ahi : g_xhi;
    const __nv_bfloat16* __restrict__ xlo = which ? g_alo : g_xlo;
    float* __restrict__ out = which ? g_buf2 : g_buf1;

    const uint32_t sb = (uint32_t)__cvta_generic_to_shared(smc);
    // ldmatrix address bases (per-thread):
    // A quadrants: M0 rows+0/k+0, M1 rows+8/k+0, M2 rows+0/k+16B, M3 rows+8/k+16B
    const uint32_t aAddr =
        sb + SA + (uint32_t)((wco + (sub & 1) * 8 + rr) * 80 + (sub >> 1) * 16);
    // B quadrants: M0 nt rows/k+0, M1 nt rows/k+16B, M2 nt+1 rows/k+0, M3 nt+1/k+16B
    const uint32_t bAddrH =
        sb + (uint32_t)((wpix + (sub >> 1) * 8 + rr) * 80 + (sub & 1) * 16);
    const uint32_t bAddrL = bAddrH + SB_LO;

    float acc[4][4][4];
#pragma unroll
    for (int i = 0; i < 4; i++)
#pragma unroll
        for (int j = 0; j < 4; j++)
#pragma unroll
            for (int k = 0; k < 4; k++) acc[i][j][k] = 0.f;

    uint4 apf[2];
#pragma unroll 1
    for (int ch = 0; ch < 8; ch++) {
        const int ci0 = ch * 32;
        __syncthreads();
        {   // B tile: 1 row/thread, hi+lo planes, + zeroed spill rows
            int r = tid, ih = h0 - 1 + (r >> 6), iw = (r & 63) - 1;
            uint4 z = make_uint4(0, 0, 0, 0);
            uint4 h0v = z, h1v = z, h2v = z, h3v = z;
            uint4 l0v = z, l1v = z, l2v = z, l3v = z;
            if ((unsigned)ih < 56u && (unsigned)iw < 56u) {
                size_t s = ((size_t)img * HWPIX + ih * 56 + iw) * 256 + ci0;
                const uint4* ph = (const uint4*)(xhi + s);
                const uint4* pl = (const uint4*)(xlo + s);
                h0v = ph[0]; h1v = ph[1]; h2v = ph[2]; h3v = ph[3];
                l0v = pl[0]; l1v = pl[1]; l2v = pl[2]; l3v = pl[3];
            }
            char* bh = smc + r * 80;
            *(uint4*)bh = h0v; *(uint4*)(bh + 16) = h1v;
            *(uint4*)(bh + 32) = h2v; *(uint4*)(bh + 48) = h3v;
            char* bl = smc + SB_LO + r * 80;
            *(uint4*)bl = l0v; *(uint4*)(bl + 16) = l1v;
            *(uint4*)(bl + 32) = l2v; *(uint4*)(bl + 48) = l3v;
            if (tid < 8) {
                int rw = 256 + (tid >> 1), q = (tid & 1) * 32;
                char* zh = smc + rw * 80 + q;
                char* zl = smc + SB_LO + rw * 80 + q;
                *(uint4*)zh = z; *(uint4*)(zh + 16) = z;
                *(uint4*)zl = z; *(uint4*)(zl + 16) = z;
            }
        }
        ldgA(apf, which, 0, co0, ci0, tid);
        stsA(smc + SA, apf, tid);
        __syncthreads();

        int ab = 0;
#pragma unroll 1
        for (int pos = 0; pos < 9; pos++) {
            if (pos < 8) ldgA(apf, which, pos + 1, co0, ci0, tid);
            const uint32_t bsh = (uint32_t)(((pos / 3) * 64 + (pos % 3)) * 80);
            const uint32_t abase = aAddr + ab * 10240;
#pragma unroll
            for (int kk = 0; kk < 2; kk++) {
                const uint32_t kb = kk * 32;
                uint32_t a[4][4];
#pragma unroll
                for (int mt = 0; mt < 4; mt++)
                    ldsm4(a[mt], abase + mt * 1280 + kb);
#pragma unroll
                for (int p = 0; p < 2; p++) {
                    uint32_t bh[4], bl[4];
                    ldsm4(bh, bAddrH + bsh + p * 1280 + kb);
                    ldsm4(bl, bAddrL + bsh + p * 1280 + kb);
#pragma unroll
                    for (int mt = 0; mt < 4; mt++) {
                        mma16816(acc[mt][2 * p], a[mt], &bh[0]);
                        mma16816(acc[mt][2 * p + 1], a[mt], &bh[2]);
                        mma16816(acc[mt][2 * p], a[mt], &bl[0]);
                        mma16816(acc[mt][2 * p + 1], a[mt], &bl[2]);
                    }
                }
            }
            if (pos < 8) {
                stsA(smc + SA + (ab ^ 1) * 10240, apf, tid);
                __syncthreads();
                ab ^= 1;
            }
        }
    }

#pragma unroll
    for (int mt = 0; mt < 4; mt++) {
        int co = co0 + wco + mt * 16 + g;
#pragma unroll
        for (int nt = 0; nt < 4; nt++) {
            int n = wpix + nt * 8 + tg * 2;
            int ow = n & 63;
            if (ow < 56) {
                size_t p = ((size_t)img * HWPIX + (h0 + (n >> 6)) * 56 + ow) * 256;
                out[p + co] = acc[mt][nt][0];
                out[p + co + 8] = acc[mt][nt][2];
                out[p + 256 + co] = acc[mt][nt][1];
                out[p + 256 + co + 8] = acc[mt][nt][3];
            }
        }
    }
}

// ---- BN / epilogue ----
__global__ void bnstat_k(int which) {
    const float* __restrict__ v = which ? g_buf2 : g_buf1;
    int c = threadIdx.x;
    const float* p = v + (size_t)blockIdx.x * 784 * 256 + c;
    double s = 0.0, qq = 0.0;
#pragma unroll 4
    for (int i = 0; i < 784; i++) {
        double f = (double)p[(size_t)i * 256];
        s += f; qq += f * f;
    }
    atomicAdd(&g_bnsum[which][c], s);
    atomicAdd(&g_bnsq[which][c], qq);
}

__global__ void bnfin_k(const float* __restrict__ gamma,
                        const float* __restrict__ beta, int which) {
    int c = threadIdx.x;
    double mean = g_bnsum[which][c] / 200704.0;
    double var = g_bnsq[which][c] / 200704.0 - mean * mean;
    if (var < 0.0) var = 0.0;
    unsigned long long wc = g_wcnt[which];
    if (!wc) wc = 1ull;
    double W = g_wsum[which] / (double)wc;
    if (W < 1e-300) W = 1e-300;
    double inv = 1.0 / sqrt(var + 1e-5 / (W * W));
    g_bnscale[which][c] = gamma[c] * (float)inv;
    g_bnshift[which][c] = beta[c] - (float)(mean * inv) * gamma[c];
}

__global__ void actprep_k() {
    size_t i4 = (size_t)blockIdx.x * 256 + threadIdx.x;
    int c0 = ((int)i4 & 63) * 4;
    float4 v = ((const float4*)g_buf1)[i4];
    float4 sc = *(const float4*)&g_bnscale[0][c0];
    float4 sh = *(const float4*)&g_bnshift[0][c0];
    float a[4];
    a[0] = fmaxf(fmaf(v.x, sc.x, sh.x), 0.f);
    a[1] = fmaxf(fmaf(v.y, sc.y, sh.y), 0.f);
    a[2] = fmaxf(fmaf(v.z, sc.z, sh.z), 0.f);
    a[3] = fmaxf(fmaf(v.w, sc.w, sh.w), 0.f);
    __nv_bfloat162 h0, h1, l0, l1;
    h0.x = __float2bfloat16(a[0]); h0.y = __float2bfloat16(a[1]);
    h1.x = __float2bfloat16(a[2]); h1.y = __float2bfloat16(a[3]);
    l0.x = __float2bfloat16(a[0] - __bfloat162float(h0.x));
    l0.y = __float2bfloat16(a[1] - __bfloat162float(h0.y));
    l1.x = __float2bfloat16(a[2] - __bfloat162float(h1.x));
    l1.y = __float2bfloat16(a[3] - __bfloat162float(h1.y));
    ((__nv_bfloat162*)g_ahi)[i4 * 2] = h0;
    ((__nv_bfloat162*)g_ahi)[i4 * 2 + 1] = h1;
    ((__nv_bfloat162*)g_alo)[i4 * 2] = l0;
    ((__nv_bfloat162*)g_alo)[i4 * 2 + 1] = l1;
}

__global__ void final_k(const float* __restrict__ x, float* __restrict__ out) {
    __shared__ float s[32][33];
    int img = blockIdx.z, c0 = blockIdx.y * 32, p0 = blockIdx.x * 32;
    int tx = threadIdx.x, ty = threadIdx.y;
#pragma unroll
    for (int r = 0; r < 4; r++) {
        int pl = ty + r * 8;
        float v = g_buf2[((size_t)img * HWPIX + p0 + pl) * 256 + c0 + tx];
        s[pl][tx] = fmaf(v, g_bnscale[1][c0 + tx], g_bnshift[1][c0 + tx]);
    }
    __syncthreads();
#pragma unroll
    for (int r = 0; r < 4; r++) {
        int cl = ty + r * 8;
        size_t o = ((size_t)img * 256 + c0 + cl) * HWPIX + p0 + tx;
        out[o] = fmaxf(s[tx][cl] + x[o], 0.f);
    }
}

// ------------------------------------------------------------------------------
extern "C" void kernel_launch(void* const* d_in, const int* in_sizes, int n_in,
                              void* d_out, int out_size) {
    const float* x  = (const float*)d_in[0];
    const float* w1 = (const float*)d_in[1];
    const float* g1 = (const float*)d_in[2];
    const float* b1 = (const float*)d_in[3];
    const float* w2 = (const float*)d_in[4];
    const float* g2 = (const float*)d_in[5];
    const float* b2 = (const float*)d_in[6];
    float* out = (float*)d_out;

    cudaFuncSetAttribute(conv_k, cudaFuncAttributeMaxDynamicSharedMemorySize, SMSZ);

    init_k<<<1, 256>>>();                                   // 1
    absmax3_k<<<dim3(1184, 3), 256>>>(w1, w2, x);           // 2
    prep_k<<<1024 + 64 * 784, 256>>>(w1, w2, x);            // 3
    dim3 cgrid(28, 2, 64);
    conv_k<<<cgrid, 256, SMSZ>>>(0);                        // 4  <- profiled
    bnstat_k<<<256, 256>>>(0);
    bnfin_k<<<1, 256>>>(g1, b1, 0);
    actprep_k<<<50176, 256>>>();
    conv_k<<<cgrid, 256, SMSZ>>>(1);
    bnstat_k<<<256, 256>>>(1);
    bnfin_k<<<1, 256>>>(g2, b2, 1);
    final_k<<<dim3(98, 8, 64), dim3(32, 8)>>>(x, out);
}

// round 16
// speedup vs baseline: 1.0020x; 1.0020x over previous
#include <cuda_runtime.h>
#include <cuda_bf16.h>
#include <cstdint>

#define HWPIX 3136
#define NELEM 51380224
#define TFAC 0.05f

__device__ __nv_bfloat16 g_xhi[NELEM], g_xlo[NELEM];
__device__ __nv_bfloat16 g_ahi[NELEM], g_alo[NELEM];
__device__ float g_buf1[NELEM], g_buf2[NELEM];
__device__ __nv_bfloat16 g_ws[2][9][65536];   // sign weights [sel][pos][co*256+ci]
__device__ unsigned g_absw[2], g_absx;
__device__ double g_wsum[2];
__device__ unsigned long long g_wcnt[2];
__device__ double g_bnsum[2][256], g_bnsq[2][256];
__device__ float g_bnscale[2][256], g_bnshift[2][256];

__device__ __forceinline__ void mma16816(float* d, const uint32_t* a,
                                         const uint32_t* b) {
    asm volatile(
        "mma.sync.aligned.m16n8k16.row.col.f32.bf16.bf16.f32 "
        "{%0,%1,%2,%3}, {%4,%5,%6,%7}, {%8,%9}, {%0,%1,%2,%3};"
        : "+f"(d[0]), "+f"(d[1]), "+f"(d[2]), "+f"(d[3])
        : "r"(a[0]), "r"(a[1]), "r"(a[2]), "r"(a[3]), "r"(b[0]), "r"(b[1]));
}
__device__ __forceinline__ void ldsm4(uint32_t* r, uint32_t addr) {
    asm volatile("ldmatrix.sync.aligned.m8n8.x4.shared.b16 {%0,%1,%2,%3}, [%4];"
                 : "=r"(r[0]), "=r"(r[1]), "=r"(r[2]), "=r"(r[3]) : "r"(addr));
}

// ---- launch 1 ----
__global__ void init_k() {
    int t = threadIdx.x;
    if (t < 2) { g_absw[t] = 0u; g_wsum[t] = 0.0; g_wcnt[t] = 0ull; }
    if (t == 2) g_absx = 0u;
    g_bnsum[0][t] = 0.0; g_bnsum[1][t] = 0.0;
    g_bnsq[0][t] = 0.0;  g_bnsq[1][t] = 0.0;
}

// ---- launch 2: absmax of w1 / w2 / x ----
__global__ void absmax3_k(const float* __restrict__ w1,
                          const float* __restrict__ w2,
                          const float* __restrict__ x) {
    int sel = blockIdx.y;
    float m = 0.f;
    if (sel < 2) {
        const float* w = sel ? w2 : w1;
        for (int i = blockIdx.x * blockDim.x + threadIdx.x; i < 589824;
             i += gridDim.x * blockDim.x)
            m = fmaxf(m, fabsf(w[i]));
    } else {
        const float4* p = (const float4*)x;
        for (size_t i = (size_t)blockIdx.x * blockDim.x + threadIdx.x;
             i < NELEM / 4; i += (size_t)gridDim.x * blockDim.x) {
            float4 v = p[i];
            m = fmaxf(m, fmaxf(fmaxf(fabsf(v.x), fabsf(v.y)),
                               fmaxf(fabsf(v.z), fabsf(v.w))));
        }
    }
#pragma unroll
    for (int o = 16; o; o >>= 1) m = fmaxf(m, __shfl_xor_sync(~0u, m, o));
    __shared__ float sm[8];
    if ((threadIdx.x & 31) == 0) sm[threadIdx.x >> 5] = m;
    __syncthreads();
    if (threadIdx.x == 0) {
        float mm = sm[0];
#pragma unroll
        for (int i = 1; i < 8; i++) mm = fmaxf(mm, sm[i]);
        atomicMax(sel < 2 ? &g_absw[sel] : &g_absx, __float_as_uint(mm));
    }
}

// ---- launch 3: wsum + wsign + xprep fused ----
__global__ void prep_k(const float* __restrict__ w1, const float* __restrict__ w2,
                       const float* __restrict__ x) {
    int b = blockIdx.x, tid = threadIdx.x;
    if (b < 512) {
        int sel = b >> 8;
        const float* w = sel ? w2 : w1;
        float th = TFAC * __uint_as_float(g_absw[sel]);
        double s = 0.0;
        unsigned c = 0;
        for (int i = (b & 255) * 256 + tid; i < 589824; i += 65536) {
            float v = w[i];
            if (v >= th || v <= -th) { s += (double)fabsf(v); c++; }
        }
#pragma unroll
        for (int o = 16; o; o >>= 1) {
            s += __shfl_xor_sync(~0u, s, o);
            c += __shfl_xor_sync(~0u, c, o);
        }
        __shared__ double ss[8];
        __shared__ unsigned sc_[8];
        if ((tid & 31) == 0) { ss[tid >> 5] = s; sc_[tid >> 5] = c; }
        __syncthreads();
        if (tid == 0) {
            double S = 0.0; unsigned long long C = 0ull;
#pragma unroll
            for (int i = 0; i < 8; i++) { S += ss[i]; C += sc_[i]; }
            atomicAdd(&g_wsum[sel], S);
            atomicAdd(&g_wcnt[sel], C);
        }
    } else if (b < 1024) {
        int sel = (b - 512) >> 8;
        const float* w = sel ? w2 : w1;
        float th = TFAC * __uint_as_float(g_absw[sel]);
        int i = ((b - 512) & 255) * 256 + tid;
#pragma unroll
        for (int k = 0; k < 9; k++) {
            float v = w[(size_t)i * 9 + k];
            float s = (v >= th) ? 1.f : ((v < -th) ? -1.f : 0.f);
            g_ws[sel][k][i] = __float2bfloat16(s);
        }
    } else {
        __shared__ float s[32][33];
        int idx = b - 1024;
        int img = idx / 784, rem = idx % 784;
        int c0 = (rem / 98) * 32, p0 = (rem % 98) * 32;
        int tx = tid & 31, ty = tid >> 5;
#pragma unroll
        for (int r = 0; r < 4; r++)
            s[ty + r * 8][tx] =
                x[((size_t)img * 256 + c0 + ty + r * 8) * HWPIX + p0 + tx];
        __syncthreads();
#pragma unroll
        for (int r = 0; r < 4; r++) {
            float v = s[tx][ty + r * 8];
            __nv_bfloat16 h = __float2bfloat16(v);
            __nv_bfloat16 l = __float2bfloat16(v - __bfloat162float(h));
            size_t d = ((size_t)img * HWPIX + p0 + ty + r * 8) * 256 + c0 + tx;
            g_xhi[d] = h; g_xlo[d] = l;
        }
    }
}

// ---- conv: CTA 128co x 128pix, bf16 HMMA, ldmatrix fragment loads ----
#define SB_LO 20800
#define SA    41600
#define SMSZ  62080

__device__ __forceinline__ void ldgA(uint4* v, int which, int pos, int co0,
                                     int ci0, int tid) {
    const uint4* p = (const uint4*)(g_ws[which][pos] +
                                    (size_t)(co0 + (tid >> 1)) * 256 + ci0 +
                                    (tid & 1) * 16);
    v[0] = p[0]; v[1] = p[1];
}
__device__ __forceinline__ void stsA(char* base, const uint4* v, int tid) {
    char* d = base + (tid >> 1) * 80 + (tid & 1) * 32;
    *(uint4*)d = v[0];
    *(uint4*)(d + 16) = v[1];
}

__global__ void __launch_bounds__(256, 2) conv_k(int which) {
    extern __shared__ char smc[];
    const int tid = threadIdx.x, lane = tid & 31, warp = tid >> 5;
    const int g = lane >> 2, tg = lane & 3;
    const int sub = lane >> 3, rr = lane & 7;
    const int wco = (warp >> 2) * 64, wpix = (warp & 3) * 32;
    const int h0 = blockIdx.x * 2, co0 = blockIdx.y * 128, img = blockIdx.z;
    const __nv_bfloat16* __restrict__ xhi = which ? g_ahi : g_xhi;
    const __nv_bfloat16* __restrict__ xlo = which ? g_alo : g_xlo;
    float* __restrict__ out = which ? g_buf2 : g_buf1;

    const uint32_t sb = (uint32_t)__cvta_generic_to_shared(smc);
    // ldmatrix address bases (per-thread):
    // A quadrants: M0 rows+0/k+0, M1 rows+8/k+0, M2 rows+0/k+16B, M3 rows+8/k+16B
    const uint32_t aAddr =
        sb + SA + (uint32_t)((wco + (sub & 1) * 8 + rr) * 80 + (sub >> 1) * 16);
    // B quadrants: M0 nt rows/k+0, M1 nt rows/k+16B, M2 nt+1 rows/k+0, M3 nt+1/k+16B
    const uint32_t bAddrH =
        sb + (uint32_t)((wpix + (sub >> 1) * 8 + rr) * 80 + (sub & 1) * 16);
    const uint32_t bAddrL = bAddrH + SB_LO;

    float acc[4][4][4];
#pragma unroll
    for (int i = 0; i < 4; i++)
#pragma unroll
        for (int j = 0; j < 4; j++)
#pragma unroll
            for (int k = 0; k < 4; k++) acc[i][j][k] = 0.f;

    uint4 apf[2];
#pragma unroll 1
    for (int ch = 0; ch < 8; ch++) {
        const int ci0 = ch * 32;
        __syncthreads();
        {   // B tile: 1 row/thread, hi+lo planes, + zeroed spill rows
            int r = tid, ih = h0 - 1 + (r >> 6), iw = (r & 63) - 1;
            uint4 z = make_uint4(0, 0, 0, 0);
            uint4 h0v = z, h1v = z, h2v = z, h3v = z;
            uint4 l0v = z, l1v = z, l2v = z, l3v = z;
            if ((unsigned)ih < 56u && (unsigned)iw < 56u) {
                size_t s = ((size_t)img * HWPIX + ih * 56 + iw) * 256 + ci0;
                const uint4* ph = (const uint4*)(xhi + s);
                const uint4* pl = (const uint4*)(xlo + s);
                h0v = ph[0]; h1v = ph[1]; h2v = ph[2]; h3v = ph[3];
                l0v = pl[0]; l1v = pl[1]; l2v = pl[2]; l3v = pl[3];
            }
            char* bh = smc + r * 80;
            *(uint4*)bh = h0v; *(uint4*)(bh + 16) = h1v;
            *(uint4*)(bh + 32) = h2v; *(uint4*)(bh + 48) = h3v;
            char* bl = smc + SB_LO + r * 80;
            *(uint4*)bl = l0v; *(uint4*)(bl + 16) = l1v;
            *(uint4*)(bl + 32) = l2v; *(uint4*)(bl + 48) = l3v;
            if (tid < 8) {
                int rw = 256 + (tid >> 1), q = (tid & 1) * 32;
                char* zh = smc + rw * 80 + q;
                char* zl = smc + SB_LO + rw * 80 + q;
                *(uint4*)zh = z; *(uint4*)(zh + 16) = z;
                *(uint4*)zl = z; *(uint4*)(zl + 16) = z;
            }
        }
        ldgA(apf, which, 0, co0, ci0, tid);
        stsA(smc + SA, apf, tid);
        __syncthreads();

        int ab = 0;
#pragma unroll 1
        for (int pos = 0; pos < 9; pos++) {
            if (pos < 8) ldgA(apf, which, pos + 1, co0, ci0, tid);
            const uint32_t bsh = (uint32_t)(((pos / 3) * 64 + (pos % 3)) * 80);
            const uint32_t abase = aAddr + ab * 10240;
#pragma unroll
            for (int kk = 0; kk < 2; kk++) {
                const uint32_t kb = kk * 32;
                uint32_t a[4][4];
#pragma unroll
                for (int mt = 0; mt < 4; mt++)
                    ldsm4(a[mt], abase + mt * 1280 + kb);
#pragma unroll
                for (int p = 0; p < 2; p++) {
                    uint32_t bh[4], bl[4];
                    ldsm4(bh, bAddrH + bsh + p * 1280 + kb);
                    ldsm4(bl, bAddrL + bsh + p * 1280 + kb);
#pragma unroll
                    for (int mt = 0; mt < 4; mt++) {
                        mma16816(acc[mt][2 * p], a[mt], &bh[0]);
                        mma16816(acc[mt][2 * p + 1], a[mt], &bh[2]);
                        mma16816(acc[mt][2 * p], a[mt], &bl[0]);
                        mma16816(acc[mt][2 * p + 1], a[mt], &bl[2]);
                    }
                }
            }
            if (pos < 8) {
                stsA(smc + SA + (ab ^ 1) * 10240, apf, tid);
                __syncthreads();
                ab ^= 1;
            }
        }
    }

#pragma unroll
    for (int mt = 0; mt < 4; mt++) {
        int co = co0 + wco + mt * 16 + g;
#pragma unroll
        for (int nt = 0; nt < 4; nt++) {
            int n = wpix + nt * 8 + tg * 2;
            int ow = n & 63;
            if (ow < 56) {
                size_t p = ((size_t)img * HWPIX + (h0 + (n >> 6)) * 56 + ow) * 256;
                out[p + co] = acc[mt][nt][0];
                out[p + co + 8] = acc[mt][nt][2];
                out[p + 256 + co] = acc[mt][nt][1];
                out[p + 256 + co + 8] = acc[mt][nt][3];
            }
        }
    }
}

// ---- BN / epilogue ----
__global__ void bnstat_k(int which) {
    const float* __restrict__ v = which ? g_buf2 : g_buf1;
    int c = threadIdx.x;
    const float* p = v + (size_t)blockIdx.x * 784 * 256 + c;
    double s = 0.0, qq = 0.0;
#pragma unroll 4
    for (int i = 0; i < 784; i++) {
        double f = (double)p[(size_t)i * 256];
        s += f; qq += f * f;
    }
    atomicAdd(&g_bnsum[which][c], s);
    atomicAdd(&g_bnsq[which][c], qq);
}

__global__ void bnfin_k(const float* __restrict__ gamma,
                        const float* __restrict__ beta, int which) {
    int c = threadIdx.x;
    double mean = g_bnsum[which][c] / 200704.0;
    double var = g_bnsq[which][c] / 200704.0 - mean * mean;
    if (var < 0.0) var = 0.0;
    unsigned long long wc = g_wcnt[which];
    if (!wc) wc = 1ull;
    double W = g_wsum[which] / (double)wc;
    if (W < 1e-300) W = 1e-300;
    double inv = 1.0 / sqrt(var + 1e-5 / (W * W));
    g_bnscale[which][c] = gamma[c] * (float)inv;
    g_bnshift[which][c] = beta[c] - (float)(mean * inv) * gamma[c];
}

__global__ void actprep_k() {
    size_t i4 = (size_t)blockIdx.x * 256 + threadIdx.x;
    int c0 = ((int)i4 & 63) * 4;
    float4 v = ((const float4*)g_buf1)[i4];
    float4 sc = *(const float4*)&g_bnscale[0][c0];
    float4 sh = *(const float4*)&g_bnshift[0][c0];
    float a[4];
    a[0] = fmaxf(fmaf(v.x, sc.x, sh.x), 0.f);
    a[1] = fmaxf(fmaf(v.y, sc.y, sh.y), 0.f);
    a[2] = fmaxf(fmaf(v.z, sc.z, sh.z), 0.f);
    a[3] = fmaxf(fmaf(v.w, sc.w, sh.w), 0.f);
    __nv_bfloat162 h0, h1, l0, l1;
    h0.x = __float2bfloat16(a[0]); h0.y = __float2bfloat16(a[1]);
    h1.x = __float2bfloat16(a[2]); h1.y = __float2bfloat16(a[3]);
    l0.x = __float2bfloat16(a[0] - __bfloat162float(h0.x));
    l0.y = __float2bfloat16(a[1] - __bfloat162float(h0.y));
    l1.x = __float2bfloat16(a[2] - __bfloat162float(h1.x));
    l1.y = __float2bfloat16(a[3] - __bfloat162float(h1.y));
    ((__nv_bfloat162*)g_ahi)[i4 * 2] = h0;
    ((__nv_bfloat162*)g_ahi)[i4 * 2 + 1] = h1;
    ((__nv_bfloat162*)g_alo)[i4 * 2] = l0;
    ((__nv_bfloat162*)g_alo)[i4 * 2 + 1] = l1;
}

__global__ void final_k(const float* __restrict__ x, float* __restrict__ out) {
    __shared__ float s[32][33];
    int img = blockIdx.z, c0 = blockIdx.y * 32, p0 = blockIdx.x * 32;
    int tx = threadIdx.x, ty = threadIdx.y;
#pragma unroll
    for (int r = 0; r < 4; r++) {
        int pl = ty + r * 8;
        float v = g_buf2[((size_t)img * HWPIX + p0 + pl) * 256 + c0 + tx];
        s[pl][tx] = fmaf(v, g_bnscale[1][c0 + tx], g_bnshift[1][c0 + tx]);
    }
    __syncthreads();
#pragma unroll
    for (int r = 0; r < 4; r++) {
        int cl = ty + r * 8;
        size_t o = ((size_t)img * 256 + c0 + cl) * HWPIX + p0 + tx;
        out[o] = fmaxf(s[tx][cl] + x[o], 0.f);
    }
}

// ------------------------------------------------------------------------------
extern "C" void kernel_launch(void* const* d_in, const int* in_sizes, int n_in,
                              void* d_out, int out_size) {
    const float* x  = (const float*)d_in[0];
    const float* w1 = (const float*)d_in[1];
    const float* g1 = (const float*)d_in[2];
    const float* b1 = (const float*)d_in[3];
    const float* w2 = (const float*)d_in[4];
    const float* g2 = (const float*)d_in[5];
    const float* b2 = (const float*)d_in[6];
    float* out = (float*)d_out;

    cudaFuncSetAttribute(conv_k, cudaFuncAttributeMaxDynamicSharedMemorySize, SMSZ);

    init_k<<<1, 256>>>();                                   // 1
    absmax3_k<<<dim3(1184, 3), 256>>>(w1, w2, x);           // 2
    prep_k<<<1024 + 64 * 784, 256>>>(w1, w2, x);            // 3
    dim3 cgrid(28, 2, 64);
    conv_k<<<cgrid, 256, SMSZ>>>(0);                        // 4  <- profiled
    bnstat_k<<<256, 256>>>(0);
    bnfin_k<<<1, 256>>>(g1, b1, 0);
    actprep_k<<<50176, 256>>>();
    conv_k<<<cgrid, 256, SMSZ>>>(1);
    bnstat_k<<<256, 256>>>(1);
    bnfin_k<<<1, 256>>>(g2, b2, 1);
    final_k<<<dim3(98, 8, 64), dim3(32, 8)>>>(x, out);
}